// round 16
// baseline (speedup 1.0000x reference)
#include <cuda_runtime.h>
#include <cstdint>

#define B_ 8
#define L_ 8192
#define D_ 256

__device__ float g_kvsT[B_ * D_ * D_];            // [b][d][m] fp32 accum
__device__ float g_ksum[B_ * D_];                 // [b][m] fp32
__device__ uint16_t g_q16[(size_t)B_ * L_ * D_];  // relu'(Q) fp16 [b][l][m]
__device__ uint16_t g_kv16[B_ * D_ * D_];         // kvsT fp16 [b][d][m]
__device__ uint16_t g_ks16[B_ * D_];              // ksum fp16 [b][m]

__device__ __forceinline__ float relu_eps(float x) { return fmaxf(x, 0.0f) + 1e-3f; }
__device__ __forceinline__ uint32_t pack_f16(float lo, float hi) {
    uint32_t r;
    asm("cvt.rn.f16x2.f32 %0, %1, %2;" : "=r"(r) : "f"(hi), "f"(lo));
    return r;
}
__device__ __forceinline__ uint32_t smem_u32(const void* p) {
    uint32_t a;
    asm("{ .reg .u64 t; cvta.to.shared.u64 t, %1; cvt.u32.u64 %0, t; }" : "=r"(a) : "l"(p));
    return a;
}
__device__ __forceinline__ void cpa16(uint32_t s, const void* g) {
    asm volatile("cp.async.cg.shared.global [%0], [%1], 16;" :: "r"(s), "l"(g));
}
#define CP_COMMIT() asm volatile("cp.async.commit_group;" ::: "memory")
#define CP_WAIT1()  asm volatile("cp.async.wait_group 1;" ::: "memory")
#define CP_WAIT0()  asm volatile("cp.async.wait_group 0;" ::: "memory")

__device__ __forceinline__ void mma16(float* c, const uint32_t* a, const uint32_t* b) {
    asm volatile("mma.sync.aligned.m16n8k16.row.col.f32.f16.f16.f32 "
        "{%0,%1,%2,%3}, {%4,%5,%6,%7}, {%8,%9}, {%0,%1,%2,%3};"
        : "+f"(c[0]), "+f"(c[1]), "+f"(c[2]), "+f"(c[3])
        : "r"(a[0]), "r"(a[1]), "r"(a[2]), "r"(a[3]), "r"(b[0]), "r"(b[1]));
}
#define LDSM4(r0, r1, r2, r3, a) \
    asm volatile("ldmatrix.sync.aligned.m8n8.x4.shared.b16 {%0,%1,%2,%3}, [%4];" \
        : "=r"(r0), "=r"(r1), "=r"(r2), "=r"(r3) : "r"(a))
#define LDSM4T(r0, r1, r2, r3, a) \
    asm volatile("ldmatrix.sync.aligned.m8n8.x4.trans.shared.b16 {%0,%1,%2,%3}, [%4];" \
        : "=r"(r0), "=r"(r1), "=r"(r2), "=r"(r3) : "r"(a))
#define STS2(a, p0, p1) \
    asm volatile("st.shared.v2.u32 [%0], {%1,%2};" :: "r"(a), "r"(p0), "r"(p1))

#define TSTR 132     // pass1 fp32 staging [32 l][128] tiles
#define PITCH16 272  // pass1 fp16 tile row pitch bytes
#define F32BYTES (4 * 32 * TSTR * 4)
#define K16OFF F32BYTES
#define V16OFF (F32BYTES + 32 * PITCH16)
#define P1_SMEM (F32BYTES + 2 * 32 * PITCH16)

// pass2 smem: Q16 [2][128][64B] + KV16 [2][128][64B] + ks16 [512B]
#define P2KV 16384
#define P2KS 32768
#define P2_SMEM (32768 + 512)
// chunk swizzle within a 64B row: j' = j ^ ((row>>1)&3)
#define SWZ(row, j) ((uint32_t)(((row) << 6) + ((((j) ^ (((row) >> 1) & 3))) << 4)))

// ---------------------------------------------------------------------------
__global__ void zero_kernel() {
    int i = blockIdx.x * 256 + threadIdx.x;
    float4 z = {0.f, 0.f, 0.f, 0.f};
    if (i < B_ * D_ * D_ / 4) ((float4*)g_kvsT)[i] = z;
    if (i < B_ * D_ / 4) ((float4*)g_ksum)[i] = z;
}

// quantKV: kvsT fp32 -> kv16; ksum fp32 -> ks16. grid (17, B), 256 thr.
__global__ void __launch_bounds__(256) quantkv_kernel() {
    int b = blockIdx.y;
    if (blockIdx.x < 16) {
        size_t base = (size_t)b * D_ * D_ + blockIdx.x * 16 * D_;
#pragma unroll
        for (int i = 0; i < 4; i++) {
            int id = threadIdx.x + i * 256;
            float4 v = *(const float4*)&g_kvsT[base + id * 4];
            *(uint2*)&g_kv16[base + id * 4] =
                make_uint2(pack_f16(v.x, v.y), pack_f16(v.z, v.w));
        }
    } else if (threadIdx.x < 64) {
        int t = threadIdx.x;
        float4 v = *(const float4*)&g_ksum[b * D_ + t * 4];
        *(uint2*)&g_ks16[b * D_ + t * 4] =
            make_uint2(pack_f16(v.x, v.y), pack_f16(v.z, v.w));
    }
}

// ---------------------------------------------------------------------------
// Pass 1: kvsT += relu'(K)^T V (fused ksum) + piggybacked Q quantization.
// grid (4, 8 lchunks, B), 128 thr, warp tile 64m x 64d (R15 structure).
__global__ void __launch_bounds__(128, 2) pass1_mma(const float* __restrict__ K,
                                                    const float* __restrict__ V,
                                                    const float* __restrict__ Q) {
    extern __shared__ float sm[];
    const int t = threadIdx.x, lane = t & 31, w = t >> 5;
    const int g = lane >> 2, tg = lane & 3;
    const int bx = blockIdx.x;
    const int m0 = (bx & 1) * 128, d0 = (bx >> 1) * 128;
    const int b = blockIdx.z;
    const int lbase = blockIdx.y * 1024;
    const int wm = (w & 1) * 64, wd = (w >> 1) * 64;
    const bool do_ksum = (bx >> 1) == 0;

    float acc[4][8][4] = {};
    float4 ksa = {0.f, 0.f, 0.f, 0.f};

    const uint32_t sb = smem_u32(sm);
    const uint32_t aK16 = sb + K16OFF, aV16 = sb + V16OFF;
    const float* Kg = K + (size_t)b * L_ * D_ + m0;
    const float* Vg = V + (size_t)b * L_ * D_ + d0;
    const float* Qg = Q + (size_t)b * L_ * D_ + bx * 64;
    uint16_t* q16o = g_q16 + (size_t)b * L_ * D_ + bx * 64;

    const int la = ((lane >> 4) & 1) * 8 + (lane & 7);
    const int ma = ((lane >> 3) & 1) * 8;
    const int lb = ((lane >> 3) & 1) * 8 + (lane & 7);
    const int db = ((lane >> 4) & 1) * 8;

    auto prefetch = [&](int s) {
        int buf = s & 1;
        uint32_t kb = sb + (uint32_t)(buf * 32 * TSTR) * 4;
        uint32_t vb = sb + (uint32_t)((2 + buf) * 32 * TSTR) * 4;
        const float* kg = Kg + (size_t)(lbase + s * 32) * D_;
        const float* vg = Vg + (size_t)(lbase + s * 32) * D_;
#pragma unroll
        for (int i = 0; i < 8; i++) {
            int j = t + i * 128, row = j >> 5, c = j & 31;
            uint32_t off = (uint32_t)(row * TSTR + c * 4) * 4;
            cpa16(kb + off, kg + (size_t)row * D_ + c * 4);
            cpa16(vb + off, vg + (size_t)row * D_ + c * 4);
        }
        CP_COMMIT();
    };

    prefetch(0);
    prefetch(1);

    const int S = 32;
    for (int s = 0; s < S; s++) {
        int buf = s & 1;
        if (s >= S - 2) { CP_WAIT0(); } else { CP_WAIT1(); }
        const float* Kb = sm + buf * 32 * TSTR;
        const float* Vb = sm + (2 + buf) * 32 * TSTR;
#pragma unroll
        for (int i = 0; i < 8; i++) {
            int j = t + i * 128, row = j >> 5, c = j & 31;
            float4 kv = *(const float4*)&Kb[row * TSTR + c * 4];
            kv.x = relu_eps(kv.x); kv.y = relu_eps(kv.y);
            kv.z = relu_eps(kv.z); kv.w = relu_eps(kv.w);
            if (do_ksum) { ksa.x += kv.x; ksa.y += kv.y; ksa.z += kv.z; ksa.w += kv.w; }
            STS2(aK16 + (uint32_t)(row * PITCH16 + c * 8),
                 pack_f16(kv.x, kv.y), pack_f16(kv.z, kv.w));
            float4 vv = *(const float4*)&Vb[row * TSTR + c * 4];
            STS2(aV16 + (uint32_t)(row * PITCH16 + c * 8),
                 pack_f16(vv.x, vv.y), pack_f16(vv.z, vv.w));
        }
        __syncthreads();
        if (s + 2 < S) prefetch(s + 2);

        // piggyback: quantize Q slice rows (lbase+s*32 .. +32), cols bx*64..+64
        {
            const float* qs = Qg + (size_t)(lbase + s * 32) * D_;
            uint16_t* qo = q16o + (size_t)(lbase + s * 32) * D_;
#pragma unroll
            for (int i = 0; i < 4; i++) {
                int id = t + i * 128, row = id >> 4, c = id & 15;
                float4 q = *(const float4*)(qs + (size_t)row * D_ + c * 4);
                q.x = relu_eps(q.x); q.y = relu_eps(q.y);
                q.z = relu_eps(q.z); q.w = relu_eps(q.w);
                *(uint2*)(qo + (size_t)row * D_ + c * 4) =
                    make_uint2(pack_f16(q.x, q.y), pack_f16(q.z, q.w));
            }
        }

#pragma unroll
        for (int kk = 0; kk < 2; kk++) {
            int kb16 = kk * 16;
            uint32_t Au[4][4];
#pragma unroll
            for (int mi = 0; mi < 4; mi++) {
                uint32_t a = aK16 + (uint32_t)((kb16 + la) * PITCH16 + (wm + mi * 16 + ma) * 2);
                LDSM4T(Au[mi][0], Au[mi][1], Au[mi][2], Au[mi][3], a);
            }
            uint32_t Bf[8][2];
#pragma unroll
            for (int nj = 0; nj < 4; nj++) {
                uint32_t a = aV16 + (uint32_t)((kb16 + lb) * PITCH16 + (wd + nj * 16 + db) * 2);
                LDSM4T(Bf[2 * nj][0], Bf[2 * nj][1], Bf[2 * nj + 1][0], Bf[2 * nj + 1][1], a);
            }
#pragma unroll
            for (int mi = 0; mi < 4; mi++)
#pragma unroll
                for (int ni = 0; ni < 8; ni++) mma16(acc[mi][ni], Au[mi], Bf[ni]);
        }
        __syncthreads();
    }

    if (do_ksum) {
        float* kp = &g_ksum[b * D_ + m0 + (t & 31) * 4];
        atomicAdd(kp + 0, ksa.x); atomicAdd(kp + 1, ksa.y);
        atomicAdd(kp + 2, ksa.z); atomicAdd(kp + 3, ksa.w);
    }

    float* base = &g_kvsT[(size_t)b * D_ * D_];
#pragma unroll
    for (int mi = 0; mi < 4; mi++) {
        int mrow = m0 + wm + mi * 16 + g;
#pragma unroll
        for (int ni = 0; ni < 8; ni++) {
            int dc = d0 + wd + ni * 8 + 2 * tg;
            atomicAdd(base + (size_t)dc * D_ + mrow, acc[mi][ni][0]);
            atomicAdd(base + (size_t)(dc + 1) * D_ + mrow, acc[mi][ni][1]);
            atomicAdd(base + (size_t)dc * D_ + mrow + 8, acc[mi][ni][2]);
            atomicAdd(base + (size_t)(dc + 1) * D_ + mrow + 8, acc[mi][ni][3]);
        }
    }
}

// ---------------------------------------------------------------------------
// Pass 2 (fp16 end-to-end): out[l][d] = (q16 . kv16) / (q16 . ks16)
// grid (64 ltiles, 2 dtiles, B), 128 thr, warp tile 64l x 64d.
// cp.async fills swizzled fp16 tiles; ldmatrix x4 non-trans; norm via extra MMA.
__global__ void __launch_bounds__(128, 2) pass2_mma(float* __restrict__ out) {
    extern __shared__ float sm[];
    const int t = threadIdx.x, lane = t & 31, w = t >> 5;
    const int g = lane >> 2, tg = lane & 3;
    const int b = blockIdx.z;
    const int l0 = blockIdx.x * 128, d0 = blockIdx.y * 128;
    const int wl = (w & 1) * 64, wd = (w >> 1) * 64;

    float acc[4][8][4] = {};
    float nacc[4][4] = {};

    const uint32_t sb = smem_u32(sm);
    const uint16_t* Qg = g_q16 + ((size_t)b * L_ + l0) * D_;
    const uint16_t* KVg = g_kv16 + ((size_t)b * D_ + d0) * D_;

    auto prefetch = [&](int s) {
        int buf = s & 1;
        uint32_t qb = sb + buf * 8192;
        uint32_t kb = sb + P2KV + buf * 8192;
        int mb = s * 32;
#pragma unroll
        for (int i = 0; i < 4; i++) {
            int id = t + i * 128, row = id >> 2, j = id & 3;
            uint32_t dst = SWZ(row, j);
            cpa16(qb + dst, Qg + (size_t)row * D_ + mb + 8 * j);
            cpa16(kb + dst, KVg + (size_t)row * D_ + mb + 8 * j);
        }
        CP_COMMIT();
    };

    // stage ks16 into smem (128 words = 256 halves)
    if (t < 128)
        *(uint32_t*)((char*)sm + P2KS + t * 4) =
            *(const uint32_t*)(g_ks16 + b * D_ + t * 2);

    prefetch(0);
    prefetch(1);

    const uint32_t ks_w = sb + P2KS;
    const int rowA = (lane & 15), selA = (lane >> 4) & 1;
    const int rowB = (lane & 7) + ((lane >> 4) << 3), selB = (lane >> 3) & 1;

    const int S = 8;
    for (int s = 0; s < S; s++) {
        int buf = s & 1;
        if (s >= S - 2) { CP_WAIT0(); } else { CP_WAIT1(); }
        __syncthreads();
        uint32_t qb = sb + buf * 8192;
        uint32_t kb = sb + P2KV + buf * 8192;
        int mbw = s * 16;  // ks word base for this stage (32 halves)
#pragma unroll
        for (int kk = 0; kk < 2; kk++) {
            uint32_t Au[4][4];
#pragma unroll
            for (int mi = 0; mi < 4; mi++) {
                int row = wl + mi * 16 + rowA;
                LDSM4(Au[mi][0], Au[mi][1], Au[mi][2], Au[mi][3],
                      qb + SWZ(row, kk * 2 + selA));
            }
            uint32_t Bf[8][2];
#pragma unroll
            for (int nj = 0; nj < 4; nj++) {
                int row = wd + nj * 16 + rowB;
                LDSM4(Bf[2 * nj][0], Bf[2 * nj][1], Bf[2 * nj + 1][0], Bf[2 * nj + 1][1],
                      kb + SWZ(row, kk * 2 + selB));
            }
            uint32_t Bs[2];
            asm volatile("ld.shared.b32 %0, [%1];" : "=r"(Bs[0])
                         : "r"(ks_w + (uint32_t)(mbw + kk * 8 + tg) * 4));
            asm volatile("ld.shared.b32 %0, [%1];" : "=r"(Bs[1])
                         : "r"(ks_w + (uint32_t)(mbw + kk * 8 + tg + 4) * 4));
#pragma unroll
            for (int mi = 0; mi < 4; mi++) {
#pragma unroll
                for (int ni = 0; ni < 8; ni++) mma16(acc[mi][ni], Au[mi], Bf[ni]);
                mma16(nacc[mi], Au[mi], Bs);
            }
        }
        __syncthreads();
        if (s + 2 < S) prefetch(s + 2);
    }

#pragma unroll
    for (int mi = 0; mi < 4; mi++) {
        float inv0 = 1.0f / nacc[mi][0];
        float inv1 = 1.0f / nacc[mi][2];
        int lr = l0 + wl + mi * 16 + g;
#pragma unroll
        for (int ni = 0; ni < 8; ni++) {
            int dc = d0 + wd + ni * 8 + 2 * tg;
            float2 v0 = {acc[mi][ni][0] * inv0, acc[mi][ni][1] * inv0};
            float2 v1 = {acc[mi][ni][2] * inv1, acc[mi][ni][3] * inv1};
            *(float2*)&out[((size_t)b * L_ + lr) * D_ + dc] = v0;
            *(float2*)&out[((size_t)b * L_ + lr + 8) * D_ + dc] = v1;
        }
    }
}

// ---------------------------------------------------------------------------
extern "C" void kernel_launch(void* const* d_in, const int* in_sizes, int n_in,
                              void* d_out, int out_size) {
    const float* queries = (const float*)d_in[0];
    const float* keys    = (const float*)d_in[1];
    const float* values  = (const float*)d_in[2];
    float* out = (float*)d_out;

    cudaFuncSetAttribute(pass1_mma, cudaFuncAttributeMaxDynamicSharedMemorySize, P1_SMEM);
    cudaFuncSetAttribute(pass2_mma, cudaFuncAttributeMaxDynamicSharedMemorySize, P2_SMEM);

    // 4 launches: profiler slot (index 3) lands on pass2_mma.
    zero_kernel<<<(B_ * D_ * D_ / 4 + 255) / 256, 256>>>();
    pass1_mma<<<dim3(4, 8, B_), 128, P1_SMEM>>>(keys, values, queries);
    quantkv_kernel<<<dim3(17, B_), 256>>>();
    pass2_mma<<<dim3(L_ / 128, 2, B_), 128, P2_SMEM>>>(out);
}

// round 17
// speedup vs baseline: 1.1207x; 1.1207x over previous
#include <cuda_runtime.h>
#include <cstdint>

#define B_ 8
#define L_ 8192
#define D_ 256

__device__ float g_kvsT[B_ * D_ * D_];   // [b][d][m] fp32 accum
__device__ float g_ksum[B_ * D_];        // [b][m] fp32
__device__ uint16_t g_kv16[B_ * D_ * D_];  // kvsT fp16
__device__ uint16_t g_ks16[B_ * D_];       // ksum fp16

__device__ __forceinline__ float relu_eps(float x) { return fmaxf(x, 0.0f) + 1e-3f; }
__device__ __forceinline__ uint32_t pack_f16(float lo, float hi) {
    uint32_t r;
    asm("cvt.rn.f16x2.f32 %0, %1, %2;" : "=r"(r) : "f"(hi), "f"(lo));
    return r;
}
__device__ __forceinline__ uint32_t smem_u32(const void* p) {
    uint32_t a;
    asm("{ .reg .u64 t; cvta.to.shared.u64 t, %1; cvt.u32.u64 %0, t; }" : "=r"(a) : "l"(p));
    return a;
}
__device__ __forceinline__ void cpa16(uint32_t s, const void* g) {
    asm volatile("cp.async.cg.shared.global [%0], [%1], 16;" :: "r"(s), "l"(g));
}
#define CP_COMMIT() asm volatile("cp.async.commit_group;" ::: "memory")
#define CP_WAIT1()  asm volatile("cp.async.wait_group 1;" ::: "memory")
#define CP_WAIT0()  asm volatile("cp.async.wait_group 0;" ::: "memory")

__device__ __forceinline__ void mma16(float* c, const uint32_t* a, const uint32_t* b) {
    asm volatile("mma.sync.aligned.m16n8k16.row.col.f32.f16.f16.f32 "
        "{%0,%1,%2,%3}, {%4,%5,%6,%7}, {%8,%9}, {%0,%1,%2,%3};"
        : "+f"(c[0]), "+f"(c[1]), "+f"(c[2]), "+f"(c[3])
        : "r"(a[0]), "r"(a[1]), "r"(a[2]), "r"(a[3]), "r"(b[0]), "r"(b[1]));
}
#define LDSM4(r0, r1, r2, r3, a) \
    asm volatile("ldmatrix.sync.aligned.m8n8.x4.shared.b16 {%0,%1,%2,%3}, [%4];" \
        : "=r"(r0), "=r"(r1), "=r"(r2), "=r"(r3) : "r"(a))
#define LDSM4T(r0, r1, r2, r3, a) \
    asm volatile("ldmatrix.sync.aligned.m8n8.x4.trans.shared.b16 {%0,%1,%2,%3}, [%4];" \
        : "=r"(r0), "=r"(r1), "=r"(r2), "=r"(r3) : "r"(a))
#define STS2(a, p0, p1) \
    asm volatile("st.shared.v2.u32 [%0], {%1,%2};" :: "r"(a), "r"(p0), "r"(p1))

#define TSTR 132     // pass1 fp32 staging
#define PITCH16 272  // pass1 fp16 tiles
#define F32BYTES (4 * 32 * TSTR * 4)
#define K16OFF F32BYTES
#define V16OFF (F32BYTES + 32 * PITCH16)
#define P1_SMEM (F32BYTES + 2 * 32 * PITCH16)

// pass2 smem: Qf32 [2][128][QSTR=40] + KV16 [2][128][64B] + ks16 [512B]
#define QSTR 40
#define P2QBUF (128 * QSTR * 4)          // 20480 per buffer
#define P2KV (2 * P2QBUF)                 // 40960
#define P2KS (P2KV + 16384)               // 57344
#define P2_SMEM (P2KS + 512)              // 57856
#define SWZ(row, j) ((uint32_t)(((row) << 6) + ((((j) ^ (((row) >> 1) & 3))) << 4)))

// ---------------------------------------------------------------------------
__global__ void zero_kernel() {
    int i = blockIdx.x * 256 + threadIdx.x;
    float4 z = {0.f, 0.f, 0.f, 0.f};
    if (i < B_ * D_ * D_ / 4) ((float4*)g_kvsT)[i] = z;
    if (i < B_ * D_ / 4) ((float4*)g_ksum)[i] = z;
}

__global__ void __launch_bounds__(256) quantkv_kernel() {
    int b = blockIdx.y;
    if (blockIdx.x < 16) {
        size_t base = (size_t)b * D_ * D_ + blockIdx.x * 16 * D_;
#pragma unroll
        for (int i = 0; i < 4; i++) {
            int id = threadIdx.x + i * 256;
            float4 v = *(const float4*)&g_kvsT[base + id * 4];
            *(uint2*)&g_kv16[base + id * 4] =
                make_uint2(pack_f16(v.x, v.y), pack_f16(v.z, v.w));
        }
    } else if (threadIdx.x < 64) {
        int t = threadIdx.x;
        float4 v = *(const float4*)&g_ksum[b * D_ + t * 4];
        *(uint2*)&g_ks16[b * D_ + t * 4] =
            make_uint2(pack_f16(v.x, v.y), pack_f16(v.z, v.w));
    }
}

// ---------------------------------------------------------------------------
// Pass 1 (R15 verbatim): kvsT += relu'(K)^T V, fused ksum.
__global__ void __launch_bounds__(128, 2) pass1_mma(const float* __restrict__ K,
                                                    const float* __restrict__ V) {
    extern __shared__ float sm[];
    const int t = threadIdx.x, lane = t & 31, w = t >> 5;
    const int g = lane >> 2, tg = lane & 3;
    const int m0 = (blockIdx.x & 1) * 128, d0 = (blockIdx.x >> 1) * 128;
    const int b = blockIdx.z;
    const int lbase = blockIdx.y * 1024;
    const int wm = (w & 1) * 64, wd = (w >> 1) * 64;
    const bool do_ksum = (blockIdx.x >> 1) == 0;

    float acc[4][8][4] = {};
    float4 ksa = {0.f, 0.f, 0.f, 0.f};

    const uint32_t sb = smem_u32(sm);
    const uint32_t aK16 = sb + K16OFF, aV16 = sb + V16OFF;
    const float* Kg = K + (size_t)b * L_ * D_ + m0;
    const float* Vg = V + (size_t)b * L_ * D_ + d0;

    const int la = ((lane >> 4) & 1) * 8 + (lane & 7);
    const int ma = ((lane >> 3) & 1) * 8;
    const int lb = ((lane >> 3) & 1) * 8 + (lane & 7);
    const int db = ((lane >> 4) & 1) * 8;

    auto prefetch = [&](int s) {
        int buf = s & 1;
        uint32_t kb = sb + (uint32_t)(buf * 32 * TSTR) * 4;
        uint32_t vb = sb + (uint32_t)((2 + buf) * 32 * TSTR) * 4;
        const float* kg = Kg + (size_t)(lbase + s * 32) * D_;
        const float* vg = Vg + (size_t)(lbase + s * 32) * D_;
#pragma unroll
        for (int i = 0; i < 8; i++) {
            int j = t + i * 128, row = j >> 5, c = j & 31;
            uint32_t off = (uint32_t)(row * TSTR + c * 4) * 4;
            cpa16(kb + off, kg + (size_t)row * D_ + c * 4);
            cpa16(vb + off, vg + (size_t)row * D_ + c * 4);
        }
        CP_COMMIT();
    };

    prefetch(0);
    prefetch(1);

    const int S = 32;
    for (int s = 0; s < S; s++) {
        int buf = s & 1;
        if (s >= S - 2) { CP_WAIT0(); } else { CP_WAIT1(); }
        const float* Kb = sm + buf * 32 * TSTR;
        const float* Vb = sm + (2 + buf) * 32 * TSTR;
#pragma unroll
        for (int i = 0; i < 8; i++) {
            int j = t + i * 128, row = j >> 5, c = j & 31;
            float4 kv = *(const float4*)&Kb[row * TSTR + c * 4];
            kv.x = relu_eps(kv.x); kv.y = relu_eps(kv.y);
            kv.z = relu_eps(kv.z); kv.w = relu_eps(kv.w);
            if (do_ksum) { ksa.x += kv.x; ksa.y += kv.y; ksa.z += kv.z; ksa.w += kv.w; }
            STS2(aK16 + (uint32_t)(row * PITCH16 + c * 8),
                 pack_f16(kv.x, kv.y), pack_f16(kv.z, kv.w));
            float4 vv = *(const float4*)&Vb[row * TSTR + c * 4];
            STS2(aV16 + (uint32_t)(row * PITCH16 + c * 8),
                 pack_f16(vv.x, vv.y), pack_f16(vv.z, vv.w));
        }
        __syncthreads();
        if (s + 2 < S) prefetch(s + 2);

#pragma unroll
        for (int kk = 0; kk < 2; kk++) {
            int kb16 = kk * 16;
            uint32_t Au[4][4];
#pragma unroll
            for (int mi = 0; mi < 4; mi++) {
                uint32_t a = aK16 + (uint32_t)((kb16 + la) * PITCH16 + (wm + mi * 16 + ma) * 2);
                LDSM4T(Au[mi][0], Au[mi][1], Au[mi][2], Au[mi][3], a);
            }
            uint32_t Bf[8][2];
#pragma unroll
            for (int nj = 0; nj < 4; nj++) {
                uint32_t a = aV16 + (uint32_t)((kb16 + lb) * PITCH16 + (wd + nj * 16 + db) * 2);
                LDSM4T(Bf[2 * nj][0], Bf[2 * nj][1], Bf[2 * nj + 1][0], Bf[2 * nj + 1][1], a);
            }
#pragma unroll
            for (int mi = 0; mi < 4; mi++)
#pragma unroll
                for (int ni = 0; ni < 8; ni++) mma16(acc[mi][ni], Au[mi], Bf[ni]);
        }
        __syncthreads();
    }

    if (do_ksum) {
        float* kp = &g_ksum[b * D_ + m0 + (t & 31) * 4];
        atomicAdd(kp + 0, ksa.x); atomicAdd(kp + 1, ksa.y);
        atomicAdd(kp + 2, ksa.z); atomicAdd(kp + 3, ksa.w);
    }

    float* base = &g_kvsT[(size_t)b * D_ * D_];
#pragma unroll
    for (int mi = 0; mi < 4; mi++) {
        int mrow = m0 + wm + mi * 16 + g;
#pragma unroll
        for (int ni = 0; ni < 8; ni++) {
            int dc = d0 + wd + ni * 8 + 2 * tg;
            atomicAdd(base + (size_t)dc * D_ + mrow, acc[mi][ni][0]);
            atomicAdd(base + (size_t)(dc + 1) * D_ + mrow, acc[mi][ni][1]);
            atomicAdd(base + (size_t)dc * D_ + mrow + 8, acc[mi][ni][2]);
            atomicAdd(base + (size_t)(dc + 1) * D_ + mrow + 8, acc[mi][ni][3]);
        }
    }
}

// ---------------------------------------------------------------------------
// Pass 2: 256 thr, 8 warps (4l x 2d), warp tile 32l x 64d.
// A: fp32 Q cp.async -> LDS.64 + relu + pack (register-side).
// B: kv16 cp.async swizzled -> LDSM non-trans. Norm: MMA vs ks16 frag.
__global__ void __launch_bounds__(256, 2) pass2_mma(const float* __restrict__ Q,
                                                    float* __restrict__ out) {
    extern __shared__ float sm[];
    const int t = threadIdx.x, lane = t & 31, w = t >> 5;
    const int g = lane >> 2, tg = lane & 3;
    const int b = blockIdx.z;
    const int l0 = blockIdx.x * 128, d0 = blockIdx.y * 128;
    const int wl = (w & 3) * 32, wd = (w >> 2) * 64;

    float acc[2][8][4] = {};
    float nacc[2][4] = {};

    const uint32_t sb = smem_u32(sm);
    const float* Qg = Q + ((size_t)b * L_ + l0) * D_;
    const uint16_t* KVg = g_kv16 + ((size_t)b * D_ + d0) * D_;

    auto prefetch = [&](int s) {
        int buf = s & 1;
        uint32_t qb = sb + buf * P2QBUF;
        uint32_t kb = sb + P2KV + buf * 8192;
        int mb = s * 32;
#pragma unroll
        for (int i = 0; i < 4; i++) {  // Q fp32: 1024 chunks / 256 thr
            int id = t + i * 256, row = id >> 3, c = id & 7;
            cpa16(qb + (uint32_t)(row * QSTR + c * 4) * 4,
                  Qg + (size_t)row * D_ + mb + c * 4);
        }
#pragma unroll
        for (int i = 0; i < 2; i++) {  // KV16: 512 chunks / 256 thr
            int id = t + i * 256, row = id >> 2, j = id & 3;
            cpa16(kb + SWZ(row, j), KVg + (size_t)row * D_ + mb + 8 * j);
        }
        CP_COMMIT();
    };

    if (t < 128)
        *(uint32_t*)((char*)sm + P2KS + t * 4) =
            *(const uint32_t*)(g_ks16 + b * D_ + t * 2);

    prefetch(0);
    prefetch(1);

    const uint32_t ks_w = sb + P2KS;
    const int rowB = (lane & 7) + ((lane >> 4) << 3), selB = (lane >> 3) & 1;

    const int S = 8;
    for (int s = 0; s < S; s++) {
        int buf = s & 1;
        if (s >= S - 2) { CP_WAIT0(); } else { CP_WAIT1(); }
        __syncthreads();
        const float* Qb = sm + buf * (P2QBUF / 4);
        uint32_t kb = sb + P2KV + buf * 8192;
        int mbw = s * 16;
#pragma unroll
        for (int kk = 0; kk < 2; kk++) {
            int lo = kk * 16 + 2 * tg;
            uint32_t Au[2][4];
#pragma unroll
            for (int mi = 0; mi < 2; mi++) {
                int rA = (wl + mi * 16 + g) * QSTR;
                int rB8 = rA + 8 * QSTR;
                float2 qa0 = *(const float2*)&Qb[rA + lo];
                float2 qa8 = *(const float2*)&Qb[rA + lo + 8];
                float2 qb0 = *(const float2*)&Qb[rB8 + lo];
                float2 qb8 = *(const float2*)&Qb[rB8 + lo + 8];
                Au[mi][0] = pack_f16(relu_eps(qa0.x), relu_eps(qa0.y));
                Au[mi][1] = pack_f16(relu_eps(qb0.x), relu_eps(qb0.y));
                Au[mi][2] = pack_f16(relu_eps(qa8.x), relu_eps(qa8.y));
                Au[mi][3] = pack_f16(relu_eps(qb8.x), relu_eps(qb8.y));
            }
            uint32_t Bf[8][2];
#pragma unroll
            for (int nj = 0; nj < 4; nj++) {
                int row = wd + nj * 16 + rowB;
                LDSM4(Bf[2 * nj][0], Bf[2 * nj][1], Bf[2 * nj + 1][0], Bf[2 * nj + 1][1],
                      kb + SWZ(row, kk * 2 + selB));
            }
            uint32_t Bs[2];
            asm volatile("ld.shared.b32 %0, [%1];" : "=r"(Bs[0])
                         : "r"(ks_w + (uint32_t)(mbw + kk * 8 + tg) * 4));
            asm volatile("ld.shared.b32 %0, [%1];" : "=r"(Bs[1])
                         : "r"(ks_w + (uint32_t)(mbw + kk * 8 + tg + 4) * 4));
#pragma unroll
            for (int mi = 0; mi < 2; mi++) {
#pragma unroll
                for (int ni = 0; ni < 8; ni++) mma16(acc[mi][ni], Au[mi], Bf[ni]);
                mma16(nacc[mi], Au[mi], Bs);
            }
        }
        __syncthreads();
        if (s + 2 < S) prefetch(s + 2);
    }

#pragma unroll
    for (int mi = 0; mi < 2; mi++) {
        float inv0 = 1.0f / nacc[mi][0];
        float inv1 = 1.0f / nacc[mi][2];
        int lr = l0 + wl + mi * 16 + g;
#pragma unroll
        for (int ni = 0; ni < 8; ni++) {
            int dc = d0 + wd + ni * 8 + 2 * tg;
            float2 v0 = {acc[mi][ni][0] * inv0, acc[mi][ni][1] * inv0};
            float2 v1 = {acc[mi][ni][2] * inv1, acc[mi][ni][3] * inv1};
            *(float2*)&out[((size_t)b * L_ + lr) * D_ + dc] = v0;
            *(float2*)&out[((size_t)b * L_ + lr + 8) * D_ + dc] = v1;
        }
    }
}

// ---------------------------------------------------------------------------
extern "C" void kernel_launch(void* const* d_in, const int* in_sizes, int n_in,
                              void* d_out, int out_size) {
    const float* queries = (const float*)d_in[0];
    const float* keys    = (const float*)d_in[1];
    const float* values  = (const float*)d_in[2];
    float* out = (float*)d_out;

    cudaFuncSetAttribute(pass1_mma, cudaFuncAttributeMaxDynamicSharedMemorySize, P1_SMEM);
    cudaFuncSetAttribute(pass2_mma, cudaFuncAttributeMaxDynamicSharedMemorySize, P2_SMEM);

    // 4 launches: profiler slot (index 3) lands on pass2_mma.
    zero_kernel<<<(B_ * D_ * D_ / 4 + 255) / 256, 256>>>();
    pass1_mma<<<dim3(4, 8, B_), 128, P1_SMEM>>>(keys, values);
    quantkv_kernel<<<dim3(17, B_), 256>>>();
    pass2_mma<<<dim3(L_ / 128, 2, B_), 256, P2_SMEM>>>(queries, out);
}